// round 1
// baseline (speedup 1.0000x reference)
#include <cuda_runtime.h>
#include <math.h>

#define BB   2
#define TT   2048
#define HH   16
#define DKD  64
#define DMD  1024
#define MTOT (BB*TT)

typedef unsigned long long ull;

// ---------------- scratch (device globals: no allocation allowed) ----------
__device__ float g_q[BB*HH*TT*DKD];     // [B,H,T,DK] roped
__device__ float g_k[BB*HH*TT*DKD];     // [B,H,T,DK] roped
__device__ float g_v[BB*HH*TT*DKD];     // [B,H,T,DK]
__device__ float g_ctx[BB*TT*DMD];      // [B,T,DM] attention output
__device__ float g_cos[TT*(DKD/2)];
__device__ float g_sin[TT*(DKD/2)];

// ---------------- packed f32x2 helpers (Blackwell 2x fp32 path) ------------
__device__ __forceinline__ ull pack2(float x, float y) {
    ull r;
    asm("mov.b64 %0, {%1, %2};" : "=l"(r)
        : "r"(__float_as_uint(x)), "r"(__float_as_uint(y)));
    return r;
}
__device__ __forceinline__ void unpack2(ull v, float &x, float &y) {
    unsigned a, b;
    asm("mov.b64 {%0, %1}, %2;" : "=r"(a), "=r"(b) : "l"(v));
    x = __uint_as_float(a);
    y = __uint_as_float(b);
}
__device__ __forceinline__ ull fma2(ull a, ull b, ull c) {
    ull d;
    asm("fma.rn.f32x2 %0, %1, %2, %3;" : "=l"(d) : "l"(a), "l"(b), "l"(c));
    return d;
}
__device__ __forceinline__ ull mul2(ull a, ull b) {
    ull d;
    asm("mul.rn.f32x2 %0, %1, %2;" : "=l"(d) : "l"(a), "l"(b));
    return d;
}
__device__ __forceinline__ ull add2(ull a, ull b) {
    ull d;
    asm("add.rn.f32x2 %0, %1, %2;" : "=l"(d) : "l"(a), "l"(b));
    return d;
}

// ---------------- RoPE tables (high-precision, cheap) -----------------------
__global__ void rope_table_kernel() {
    int idx = blockIdx.x * blockDim.x + threadIdx.x;   // 0 .. T*32-1
    int t = idx >> 5;
    int i = idx & 31;
    double inv = pow(10000.0, -((double)(2 * i)) / 64.0);
    double ang = (double)t * inv;
    g_cos[idx] = (float)cos(ang);
    g_sin[idx] = (float)sin(ang);
}

// ---------------- SGEMM: C = A * W^T  (A:[M,K], W:[N,K], both K-major) ------
// 128x128 tile, BK=8, 256 threads, 8x8 per thread, f32x2 packed math.
// QKV=1: grid.z selects weight {w_q,w_k,w_v}; writes [B,H,T,DK] (+RoPE for z<2)
// QKV=0: A = g_ctx, plain row-major write to Cout.
template <int QKV>
__global__ void __launch_bounds__(256)
sgemm_kernel(const float* __restrict__ Ain,
             const float* __restrict__ W0,
             const float* __restrict__ W1,
             const float* __restrict__ W2,
             float* __restrict__ Cout)
{
    const int tid = threadIdx.x;
    const int m0 = blockIdx.y * 128;
    const int n0 = blockIdx.x * 128;
    const int z  = QKV ? (int)blockIdx.z : 0;

    const float* A = QKV ? Ain : g_ctx;
    const float* W = W0;
    if (QKV) W = (z == 0) ? W0 : ((z == 1) ? W1 : W2);

    __shared__ ull   As[8][128];   // A values duplicated into both f32x2 halves
    __shared__ float Bs[8][132];   // padded

    const int rowL = tid >> 1;          // 0..127
    const int kin  = (tid & 1) * 4;     // 0 or 4
    const float* aptr = A + (size_t)(m0 + rowL) * DMD + kin;
    const float* wptr = W + (size_t)(n0 + rowL) * DMD + kin;

    const int ty = tid >> 4;
    const int tx = tid & 15;
    const int row0 = ty * 8;
    const int col0 = tx * 8;

    ull acc[8][4];
#pragma unroll
    for (int i = 0; i < 8; i++)
#pragma unroll
        for (int j = 0; j < 4; j++) acc[i][j] = 0ull;

    for (int kt = 0; kt < DMD / 8; kt++) {
        float4 av = *(const float4*)(aptr + kt * 8);
        float4 wv = *(const float4*)(wptr + kt * 8);
        As[kin + 0][rowL] = pack2(av.x, av.x);
        As[kin + 1][rowL] = pack2(av.y, av.y);
        As[kin + 2][rowL] = pack2(av.z, av.z);
        As[kin + 3][rowL] = pack2(av.w, av.w);
        Bs[kin + 0][rowL] = wv.x;
        Bs[kin + 1][rowL] = wv.y;
        Bs[kin + 2][rowL] = wv.z;
        Bs[kin + 3][rowL] = wv.w;
        __syncthreads();

#pragma unroll
        for (int kk = 0; kk < 8; kk++) {
            ull a2[8], b2[4];
#pragma unroll
            for (int i = 0; i < 8; i++) a2[i] = As[kk][row0 + i];
            const ull* bp = (const ull*)&Bs[kk][col0];
#pragma unroll
            for (int j = 0; j < 4; j++) b2[j] = bp[j];
#pragma unroll
            for (int i = 0; i < 8; i++)
#pragma unroll
                for (int j = 0; j < 4; j++)
                    acc[i][j] = fma2(a2[i], b2[j], acc[i][j]);
        }
        __syncthreads();
    }

    // epilogue
#pragma unroll
    for (int i = 0; i < 8; i++) {
        int m = m0 + row0 + i;
#pragma unroll
        for (int j = 0; j < 4; j++) {
            float x, y;
            unpack2(acc[i][j], x, y);
            int n = n0 + col0 + 2 * j;
            if (QKV == 0) {
                *(float2*)(Cout + (size_t)m * DMD + n) = make_float2(x, y);
            } else {
                int b = m >> 11;
                int t = m & (TT - 1);
                int h = n >> 6;
                int d = n & 63;
                float* base = (z == 0) ? g_q : ((z == 1) ? g_k : g_v);
                float* dst = base + (((size_t)(b * HH + h)) * TT + t) * DKD + d;
                if (z < 2) {
                    float cs = g_cos[t * 32 + (d >> 1)];
                    float sn = g_sin[t * 32 + (d >> 1)];
                    dst[0] = x * cs - y * sn;
                    dst[1] = x * sn + y * cs;
                } else {
                    dst[0] = x;
                    dst[1] = y;
                }
            }
        }
    }
}

// ---------------- causal flash attention, fp32 (packed f32x2) --------------
// One block = 64 queries of one (b,h). One query per thread, K/V tiles in smem.
__global__ void __launch_bounds__(64)
attn_kernel()
{
    __shared__ float Ks[64][68];   // padded rows (272B: 16B aligned)
    __shared__ float Vs[64][68];

    const int qt  = blockIdx.x;
    const int h   = blockIdx.y;
    const int b   = blockIdx.z;
    const int tid = threadIdx.x;
    const int qi  = qt * 64 + tid;

    const float scale = 0.125f;  // 1/sqrt(64)

    const float* qrow = g_q + (((size_t)(b * HH + h)) * TT + qi) * DKD;
    ull q2[32];
#pragma unroll
    for (int c = 0; c < 16; c++) {
        float4 v = ((const float4*)qrow)[c];
        q2[c * 2 + 0] = pack2(v.x * scale, v.y * scale);
        q2[c * 2 + 1] = pack2(v.z * scale, v.w * scale);
    }

    ull o2[32];
#pragma unroll
    for (int i = 0; i < 32; i++) o2[i] = 0ull;
    float m = -1e30f;
    float l = 0.0f;

    const float* kb = g_k + ((size_t)(b * HH + h)) * TT * DKD;
    const float* vb = g_v + ((size_t)(b * HH + h)) * TT * DKD;

    for (int kt = 0; kt <= qt; kt++) {
        // cooperative, coalesced tile load (tile is contiguous 16KB in gmem)
        const float4* ks4 = (const float4*)(kb + (size_t)kt * 64 * DKD);
        const float4* vs4 = (const float4*)(vb + (size_t)kt * 64 * DKD);
#pragma unroll
        for (int c = 0; c < 16; c++) {
            int f4 = c * 64 + tid;          // 0..1023
            int r  = f4 >> 4;
            int c4 = f4 & 15;
            *(float4*)&Ks[r][c4 * 4] = ks4[f4];
            *(float4*)&Vs[r][c4 * 4] = vs4[f4];
        }
        __syncthreads();

        const int jend = (kt == qt) ? (tid + 1) : 64;
        for (int j = 0; j < jend; j++) {
            const ull* kr2 = (const ull*)&Ks[j][0];   // uniform addr: broadcast
            ull s0 = 0ull, s1 = 0ull, s2 = 0ull, s3 = 0ull;
#pragma unroll
            for (int d2 = 0; d2 < 32; d2 += 4) {
                s0 = fma2(q2[d2 + 0], kr2[d2 + 0], s0);
                s1 = fma2(q2[d2 + 1], kr2[d2 + 1], s1);
                s2 = fma2(q2[d2 + 2], kr2[d2 + 2], s2);
                s3 = fma2(q2[d2 + 3], kr2[d2 + 3], s3);
            }
            s0 = add2(s0, s1);
            s2 = add2(s2, s3);
            s0 = add2(s0, s2);
            float lo, hi;
            unpack2(s0, lo, hi);
            float s = lo + hi;

            if (s > m) {                    // rare after warmup
                float alpha = __expf(m - s);
                ull a2 = pack2(alpha, alpha);
                l *= alpha;
#pragma unroll
                for (int d2 = 0; d2 < 32; d2++) o2[d2] = mul2(o2[d2], a2);
                m = s;
            }
            float p = __expf(s - m);
            l += p;
            ull p2 = pack2(p, p);
            const ull* vr2 = (const ull*)&Vs[j][0];
#pragma unroll
            for (int d2 = 0; d2 < 32; d2++)
                o2[d2] = fma2(p2, vr2[d2], o2[d2]);
        }
        __syncthreads();
    }

    float invl = 1.0f / l;
    float* out = g_ctx + ((size_t)(b * TT + qi)) * DMD + h * DKD;
#pragma unroll
    for (int d2 = 0; d2 < 32; d2++) {
        float x, y;
        unpack2(o2[d2], x, y);
        out[2 * d2 + 0] = x * invl;
        out[2 * d2 + 1] = y * invl;
    }
}

// ---------------- launch ----------------------------------------------------
extern "C" void kernel_launch(void* const* d_in, const int* in_sizes, int n_in,
                              void* d_out, int out_size)
{
    const float* x   = (const float*)d_in[0];
    const float* w_q = (const float*)d_in[1];
    const float* w_k = (const float*)d_in[2];
    const float* w_v = (const float*)d_in[3];
    const float* w_o = (const float*)d_in[4];
    float* out = (float*)d_out;

    rope_table_kernel<<<(TT * 32) / 256, 256>>>();

    // fused QKV projections (+RoPE +[B,H,T,D] layout in epilogue)
    sgemm_kernel<1><<<dim3(DMD / 128, MTOT / 128, 3), 256>>>(x, w_q, w_k, w_v, nullptr);

    // causal flash attention -> g_ctx [B,T,DM]
    attn_kernel<<<dim3(TT / 64, HH, BB), 64>>>();

    // output projection
    sgemm_kernel<0><<<dim3(DMD / 128, MTOT / 128, 1), 256>>>(nullptr, w_o, nullptr, nullptr, out);
}

// round 3
// speedup vs baseline: 1.6075x; 1.6075x over previous
#include <cuda_runtime.h>
#include <cuda_bf16.h>
#include <math.h>
#include <stdint.h>

#define BB   2
#define TT   2048
#define HH   16
#define DKD  64
#define DMD  1024
#define MTOT (BB*TT)

typedef unsigned long long ull;

// ---------------- device scratch (no allocations allowed) -------------------
__device__ float g_q[BB*HH*TT*DKD];
__device__ float g_k[BB*HH*TT*DKD];
__device__ float g_v[BB*HH*TT*DKD];
__device__ float g_ctx[BB*TT*DMD];
__device__ float g_cos[TT*(DKD/2)];
__device__ float g_sin[TT*(DKD/2)];

// bf16 split operands
__device__ __nv_bfloat16 gx_hi[MTOT*DMD];
__device__ __nv_bfloat16 gx_lo[MTOT*DMD];
__device__ __nv_bfloat16 gw_hi[4*DMD*DMD];
__device__ __nv_bfloat16 gw_lo[4*DMD*DMD];
__device__ __nv_bfloat16 gctx_hi[MTOT*DMD];
__device__ __nv_bfloat16 gctx_lo[MTOT*DMD];

// ---------------- f32x2 helpers ---------------------------------------------
__device__ __forceinline__ ull pack2(float x, float y) {
    ull r;
    asm("mov.b64 %0, {%1, %2};" : "=l"(r)
        : "r"(__float_as_uint(x)), "r"(__float_as_uint(y)));
    return r;
}
__device__ __forceinline__ void unpack2(ull v, float &x, float &y) {
    unsigned a, b;
    asm("mov.b64 {%0, %1}, %2;" : "=r"(a), "=r"(b) : "l"(v));
    x = __uint_as_float(a);
    y = __uint_as_float(b);
}
__device__ __forceinline__ ull fma2(ull a, ull b, ull c) {
    ull d;
    asm("fma.rn.f32x2 %0, %1, %2, %3;" : "=l"(d) : "l"(a), "l"(b), "l"(c));
    return d;
}
__device__ __forceinline__ ull mul2(ull a, ull b) {
    ull d;
    asm("mul.rn.f32x2 %0, %1, %2;" : "=l"(d) : "l"(a), "l"(b));
    return d;
}
__device__ __forceinline__ ull add2(ull a, ull b) {
    ull d;
    asm("add.rn.f32x2 %0, %1, %2;" : "=l"(d) : "l"(a), "l"(b));
    return d;
}

// ---------------- smem / async helpers ---------------------------------------
__device__ __forceinline__ uint32_t smem_u32(const void* p) {
    uint32_t a;
    asm("{ .reg .u64 t; cvta.to.shared.u64 t, %1; cvt.u32.u64 %0, t; }"
        : "=r"(a) : "l"(p));
    return a;
}
__device__ __forceinline__ void cp_async16(uint32_t dst, const void* src) {
    asm volatile("cp.async.cg.shared.global [%0], [%1], 16;"
                 :: "r"(dst), "l"(src) : "memory");
}
#define CP_COMMIT() asm volatile("cp.async.commit_group;" ::: "memory")
#define CP_WAIT(n)  asm volatile("cp.async.wait_group %0;" :: "n"(n) : "memory")

#define LDMX4(r0, r1, r2, r3, addr) \
    asm volatile("ldmatrix.sync.aligned.m8n8.x4.shared.b16 {%0,%1,%2,%3}, [%4];" \
        : "=r"(r0), "=r"(r1), "=r"(r2), "=r"(r3) : "r"(addr))

#define MMA_BF16(d, a0, a1, a2, a3, b0, b1) \
    asm volatile("mma.sync.aligned.m16n8k16.row.col.f32.bf16.bf16.f32 " \
        "{%0,%1,%2,%3}, {%4,%5,%6,%7}, {%8,%9}, {%0,%1,%2,%3};" \
        : "+f"((d)[0]), "+f"((d)[1]), "+f"((d)[2]), "+f"((d)[3]) \
        : "r"(a0), "r"(a1), "r"(a2), "r"(a3), "r"(b0), "r"(b1))

// ---------------- RoPE tables ------------------------------------------------
__global__ void rope_table_kernel() {
    int idx = blockIdx.x * blockDim.x + threadIdx.x;
    int t = idx >> 5;
    int i = idx & 31;
    double inv = pow(10000.0, -((double)(2 * i)) / 64.0);
    double ang = (double)t * inv;
    g_cos[idx] = (float)cos(ang);
    g_sin[idx] = (float)sin(ang);
}

// ---------------- fp32 -> bf16 hi/lo split ------------------------------------
__global__ void cvt_kernel(const float2* __restrict__ src_in, int sel, int n2) {
    int i = blockIdx.x * blockDim.x + threadIdx.x;
    if (i >= n2) return;
    const float2* src = src_in;
    __nv_bfloat162* hi;
    __nv_bfloat162* lo;
    if (sel == 0)      { hi = (__nv_bfloat162*)gx_hi;   lo = (__nv_bfloat162*)gx_lo; }
    else if (sel <= 4) { hi = (__nv_bfloat162*)(gw_hi + ((size_t)(sel - 1) << 20));
                         lo = (__nv_bfloat162*)(gw_lo + ((size_t)(sel - 1) << 20)); }
    else               { hi = (__nv_bfloat162*)gctx_hi; lo = (__nv_bfloat162*)gctx_lo;
                         src = (const float2*)g_ctx; }
    float2 v = src[i];
    __nv_bfloat16 hx = __float2bfloat16(v.x);
    __nv_bfloat16 hy = __float2bfloat16(v.y);
    float rx = v.x - __bfloat162float(hx);
    float ry = v.y - __bfloat162float(hy);
    __nv_bfloat162 h; h.x = hx; h.y = hy;
    __nv_bfloat162 l; l.x = __float2bfloat16(rx); l.y = __float2bfloat16(ry);
    hi[i] = h;
    lo[i] = l;
}

// ---------------- mma.sync bf16 split GEMM: C = A * W^T ----------------------
// A:[M,1024] hi/lo, W:[N,1024] hi/lo. CTA tile 128x128, 8 warps (64x32 each).
// K chunks of 64, double-buffered cp.async. 3 passes: Ah*Bh + Ah*Bl + Al*Bh.
#define ROWB     144                     // padded row bytes (64 bf16 = 128B data)
#define TILE_B   (128 * ROWB)            // 18432
#define STAGE_B  (4 * TILE_B)            // Ah, Al, Bh, Bl
#define GEMM_SMEM (2 * STAGE_B)          // 147456

template <int QKV>
__global__ void __launch_bounds__(256, 1)
mma_gemm(float* __restrict__ Cout)
{
    extern __shared__ char smem_raw[];
    const uint32_t sb = smem_u32(smem_raw);

    const int tid = threadIdx.x;
    const int wid = tid >> 5;
    const int lid = tid & 31;
    const int n0 = blockIdx.x * 128;
    const int m0 = blockIdx.y * 128;
    const int z  = QKV ? (int)blockIdx.z : 3;

    const __nv_bfloat16* Ah = QKV ? gx_hi : gctx_hi;
    const __nv_bfloat16* Al = QKV ? gx_lo : gctx_lo;
    const __nv_bfloat16* Wh = gw_hi + ((size_t)z << 20);
    const __nv_bfloat16* Wl = gw_lo + ((size_t)z << 20);

    const __nv_bfloat16* Ah_m = Ah + (size_t)m0 * DMD;
    const __nv_bfloat16* Al_m = Al + (size_t)m0 * DMD;
    const __nv_bfloat16* Wh_n = Wh + (size_t)n0 * DMD;
    const __nv_bfloat16* Wl_n = Wl + (size_t)n0 * DMD;

    // loader indexing: 256 threads, each does 16B chunks
    const int llr = tid >> 3;            // 0..31
    const int llc = tid & 7;             // 0..7 (16B chunk in 128B of data)

    auto load_chunk = [&](int kc, int s) {
        const uint32_t stage = sb + (uint32_t)s * STAGE_B;
        const size_t koff = (size_t)kc * 64 + (size_t)llc * 8;
#pragma unroll
        for (int it = 0; it < 16; ++it) {
            const __nv_bfloat16* base =
                (it < 4) ? Ah_m : (it < 8) ? Al_m : (it < 12) ? Wh_n : Wl_n;
            const int r = (it & 3) * 32 + llr;
            const uint32_t dst = stage + (uint32_t)(it >> 2) * TILE_B
                               + (uint32_t)r * ROWB + (uint32_t)llc * 16;
            cp_async16(dst, base + (size_t)r * DMD + koff);
        }
        CP_COMMIT();
    };

    // warp tiling: 2 (m) x 4 (n)
    const int wm = wid >> 2;             // 0..1  -> 64 rows
    const int wn = wid & 3;              // 0..3  -> 32 cols
    const int lt  = lid >> 3;            // ldmatrix tile id 0..3
    const int lrw = lid & 7;             // row within 8x8 tile

    // per-lane ldmatrix base offsets (within a tile)
    const uint32_t a_off = (uint32_t)(wm * 64 + (lt & 1) * 8 + lrw) * ROWB
                         + (uint32_t)(lt >> 1) * 16;
    const uint32_t b_off = (uint32_t)(wn * 32 + (lt & 1) * 8 + lrw) * ROWB
                         + (uint32_t)(lt >> 1) * 16;

    float acc[4][4][4];
#pragma unroll
    for (int i = 0; i < 4; i++)
#pragma unroll
        for (int j = 0; j < 4; j++)
#pragma unroll
            for (int r = 0; r < 4; r++) acc[i][j][r] = 0.0f;

    load_chunk(0, 0);

    for (int c = 0; c < 16; ++c) {
        const int s = c & 1;
        if (c < 15) {
            load_chunk(c + 1, s ^ 1);
            CP_WAIT(1);
        } else {
            CP_WAIT(0);
        }
        __syncthreads();

        const uint32_t stage = sb + (uint32_t)s * STAGE_B;
        const uint32_t ah_base = stage + a_off;
        const uint32_t al_base = stage + TILE_B + a_off;
        const uint32_t bh_base = stage + 2 * TILE_B + b_off;
        const uint32_t bl_base = stage + 3 * TILE_B + b_off;

#pragma unroll
        for (int kk = 0; kk < 4; ++kk) {
            const uint32_t kb = (uint32_t)kk * 32;
            uint32_t ah[4][4], al[4][4], bh[2][4], bl[2][4];
#pragma unroll
            for (int mf = 0; mf < 4; ++mf) {
                LDMX4(ah[mf][0], ah[mf][1], ah[mf][2], ah[mf][3],
                      ah_base + (uint32_t)mf * (16 * ROWB) + kb);
                LDMX4(al[mf][0], al[mf][1], al[mf][2], al[mf][3],
                      al_base + (uint32_t)mf * (16 * ROWB) + kb);
            }
#pragma unroll
            for (int nn = 0; nn < 2; ++nn) {
                LDMX4(bh[nn][0], bh[nn][1], bh[nn][2], bh[nn][3],
                      bh_base + (uint32_t)nn * (16 * ROWB) + kb);
                LDMX4(bl[nn][0], bl[nn][1], bl[nn][2], bl[nn][3],
                      bl_base + (uint32_t)nn * (16 * ROWB) + kb);
            }
#pragma unroll
            for (int mf = 0; mf < 4; ++mf) {
#pragma unroll
                for (int nf = 0; nf < 4; ++nf) {
                    const int nn = nf >> 1;
                    const int sel = nf & 1;
                    MMA_BF16(acc[mf][nf], ah[mf][0], ah[mf][1], ah[mf][2], ah[mf][3],
                             bh[nn][sel], bh[nn][2 + sel]);
                    MMA_BF16(acc[mf][nf], ah[mf][0], ah[mf][1], ah[mf][2], ah[mf][3],
                             bl[nn][sel], bl[nn][2 + sel]);
                    MMA_BF16(acc[mf][nf], al[mf][0], al[mf][1], al[mf][2], al[mf][3],
                             bh[nn][sel], bh[nn][2 + sel]);
                }
            }
        }
        __syncthreads();
    }

    // ---------------- epilogue ----------------
    const int rbase = m0 + wm * 64 + (lid >> 2);
    const int cbase = n0 + wn * 32 + (lid & 3) * 2;

#pragma unroll
    for (int mf = 0; mf < 4; ++mf) {
#pragma unroll
        for (int nf = 0; nf < 4; ++nf) {
#pragma unroll
            for (int half = 0; half < 2; ++half) {
                const int m = rbase + mf * 16 + half * 8;
                const int n = cbase + nf * 8;
                const float x = acc[mf][nf][half * 2 + 0];
                const float y = acc[mf][nf][half * 2 + 1];
                if (QKV == 0) {
                    *(float2*)(Cout + (size_t)m * DMD + n) = make_float2(x, y);
                } else {
                    const int b = m >> 11;
                    const int t = m & (TT - 1);
                    const int h = n >> 6;
                    const int d = n & 63;
                    float* base = (z == 0) ? g_q : ((z == 1) ? g_k : g_v);
                    float* dst = base + (((size_t)(b * HH + h)) * TT + t) * DKD + d;
                    if (z < 2) {
                        const float cs = g_cos[t * 32 + (d >> 1)];
                        const float sn = g_sin[t * 32 + (d >> 1)];
                        dst[0] = x * cs - y * sn;
                        dst[1] = x * sn + y * cs;
                    } else {
                        dst[0] = x;
                        dst[1] = y;
                    }
                }
            }
        }
    }
}

// ---------------- causal flash attention, fp32 (packed f32x2) ---------------
// 128 threads = 128 queries per block; K/V 64-key tiles in smem.
__global__ void __launch_bounds__(128)
attn_kernel()
{
    __shared__ float Ks[64][68];
    __shared__ float Vs[64][68];

    const int qt  = blockIdx.x;
    const int h   = blockIdx.y;
    const int b   = blockIdx.z;
    const int tid = threadIdx.x;
    const int qi  = qt * 128 + tid;

    const float scale = 0.125f;

    const float* qrow = g_q + (((size_t)(b * HH + h)) * TT + qi) * DKD;
    ull q2[32];
#pragma unroll
    for (int c = 0; c < 16; c++) {
        float4 v = ((const float4*)qrow)[c];
        q2[c * 2 + 0] = pack2(v.x * scale, v.y * scale);
        q2[c * 2 + 1] = pack2(v.z * scale, v.w * scale);
    }

    ull o2[32];
#pragma unroll
    for (int i = 0; i < 32; i++) o2[i] = 0ull;
    float m = -1e30f;
    float l = 0.0f;

    const float* kb = g_k + ((size_t)(b * HH + h)) * TT * DKD;
    const float* vb = g_v + ((size_t)(b * HH + h)) * TT * DKD;

    const int ktiles = qt * 2 + 2;

    for (int kt = 0; kt < ktiles; kt++) {
        const float4* ks4 = (const float4*)(kb + (size_t)kt * 64 * DKD);
        const float4* vs4 = (const float4*)(vb + (size_t)kt * 64 * DKD);
#pragma unroll
        for (int c = 0; c < 8; c++) {
            int f4 = c * 128 + tid;
            int r  = f4 >> 4;
            int c4 = f4 & 15;
            *(float4*)&Ks[r][c4 * 4] = ks4[f4];
            *(float4*)&Vs[r][c4 * 4] = vs4[f4];
        }
        __syncthreads();

        int jend = qi - kt * 64 + 1;
        if (jend > 64) jend = 64;

        for (int j = 0; j < jend; j++) {
            const ull* kr2 = (const ull*)&Ks[j][0];
            ull s0 = 0ull, s1 = 0ull, s2 = 0ull, s3 = 0ull;
#pragma unroll
            for (int d2 = 0; d2 < 32; d2 += 4) {
                s0 = fma2(q2[d2 + 0], kr2[d2 + 0], s0);
                s1 = fma2(q2[d2 + 1], kr2[d2 + 1], s1);
                s2 = fma2(q2[d2 + 2], kr2[d2 + 2], s2);
                s3 = fma2(q2[d2 + 3], kr2[d2 + 3], s3);
            }
            s0 = add2(s0, s1);
            s2 = add2(s2, s3);
            s0 = add2(s0, s2);
            float lo, hi;
            unpack2(s0, lo, hi);
            float s = lo + hi;

            if (s > m) {
                float alpha = __expf(m - s);
                ull a2 = pack2(alpha, alpha);
                l *= alpha;
#pragma unroll
                for (int d2 = 0; d2 < 32; d2++) o2[d2] = mul2(o2[d2], a2);
                m = s;
            }
            float p = __expf(s - m);
            l += p;
            ull p2 = pack2(p, p);
            const ull* vr2 = (const ull*)&Vs[j][0];
#pragma unroll
            for (int d2 = 0; d2 < 32; d2++)
                o2[d2] = fma2(p2, vr2[d2], o2[d2]);
        }
        __syncthreads();
    }

    float invl = 1.0f / l;
    float* out = g_ctx + ((size_t)(b * TT + qi)) * DMD + h * DKD;
#pragma unroll
    for (int d2 = 0; d2 < 32; d2++) {
        float x, y;
        unpack2(o2[d2], x, y);
        out[2 * d2 + 0] = x * invl;
        out[2 * d2 + 1] = y * invl;
    }
}

// ---------------- launch ------------------------------------------------------
extern "C" void kernel_launch(void* const* d_in, const int* in_sizes, int n_in,
                              void* d_out, int out_size)
{
    const float* x   = (const float*)d_in[0];
    const float* w_q = (const float*)d_in[1];
    const float* w_k = (const float*)d_in[2];
    const float* w_v = (const float*)d_in[3];
    const float* w_o = (const float*)d_in[4];
    float* out = (float*)d_out;

    static int configured = 0;
    if (!configured) {
        cudaFuncSetAttribute(mma_gemm<1>, cudaFuncAttributeMaxDynamicSharedMemorySize, GEMM_SMEM);
        cudaFuncSetAttribute(mma_gemm<0>, cudaFuncAttributeMaxDynamicSharedMemorySize, GEMM_SMEM);
        configured = 1;
    }

    rope_table_kernel<<<(TT * 32) / 256, 256>>>();

    const int NX2 = MTOT * DMD / 2;
    const int NW2 = DMD * DMD / 2;
    cvt_kernel<<<(NX2 + 255) / 256, 256>>>((const float2*)x,   0, NX2);
    cvt_kernel<<<(NW2 + 255) / 256, 256>>>((const float2*)w_q, 1, NW2);
    cvt_kernel<<<(NW2 + 255) / 256, 256>>>((const float2*)w_k, 2, NW2);
    cvt_kernel<<<(NW2 + 255) / 256, 256>>>((const float2*)w_v, 3, NW2);
    cvt_kernel<<<(NW2 + 255) / 256, 256>>>((const float2*)w_o, 4, NW2);

    // QKV projections on tensor cores (+RoPE scatter)
    mma_gemm<1><<<dim3(DMD / 128, MTOT / 128, 3), 256, GEMM_SMEM>>>(nullptr);

    // causal attention
    attn_kernel<<<dim3(TT / 128, HH, BB), 128>>>();

    // ctx -> bf16 split, then output projection
    cvt_kernel<<<(NX2 + 255) / 256, 256>>>(nullptr, 5, NX2);
    mma_gemm<0><<<dim3(DMD / 128, MTOT / 128, 1), 256, GEMM_SMEM>>>(out);
}

// round 4
// speedup vs baseline: 3.0050x; 1.8694x over previous
#include <cuda_runtime.h>
#include <cuda_bf16.h>
#include <math.h>
#include <stdint.h>

#define BB   2
#define TT   2048
#define HH   16
#define DKD  64
#define DMD  1024
#define MTOT (BB*TT)

// ---------------- device scratch (no allocations allowed) -------------------
__device__ float g_cos[TT*(DKD/2)];
__device__ float g_sin[TT*(DKD/2)];

// bf16 split operands
__device__ __nv_bfloat16 gx_hi[MTOT*DMD];
__device__ __nv_bfloat16 gx_lo[MTOT*DMD];
__device__ __nv_bfloat16 gw_hi[4*DMD*DMD];
__device__ __nv_bfloat16 gw_lo[4*DMD*DMD];
__device__ __nv_bfloat16 gctx_hi[MTOT*DMD];
__device__ __nv_bfloat16 gctx_lo[MTOT*DMD];

// roped/scaled Q, roped K: [B,H,T,64]; V transposed: [B,H,64,T]
__device__ __nv_bfloat16 g_qh[BB*HH*TT*DKD];
__device__ __nv_bfloat16 g_ql[BB*HH*TT*DKD];
__device__ __nv_bfloat16 g_kh[BB*HH*TT*DKD];
__device__ __nv_bfloat16 g_kl[BB*HH*TT*DKD];
__device__ __nv_bfloat16 g_vth[BB*HH*TT*DKD];
__device__ __nv_bfloat16 g_vtl[BB*HH*TT*DKD];

// ---------------- helpers -----------------------------------------------------
__device__ __forceinline__ uint32_t smem_u32(const void* p) {
    uint32_t a;
    asm("{ .reg .u64 t; cvta.to.shared.u64 t, %1; cvt.u32.u64 %0, t; }"
        : "=r"(a) : "l"(p));
    return a;
}
__device__ __forceinline__ void cp_async16(uint32_t dst, const void* src) {
    asm volatile("cp.async.cg.shared.global [%0], [%1], 16;"
                 :: "r"(dst), "l"(src) : "memory");
}
#define CP_COMMIT() asm volatile("cp.async.commit_group;" ::: "memory")
#define CP_WAIT(n)  asm volatile("cp.async.wait_group %0;" :: "n"(n) : "memory")

#define LDMX4(r0, r1, r2, r3, addr) \
    asm volatile("ldmatrix.sync.aligned.m8n8.x4.shared.b16 {%0,%1,%2,%3}, [%4];" \
        : "=r"(r0), "=r"(r1), "=r"(r2), "=r"(r3) : "r"(addr))

#define MMA_BF16(d, a0, a1, a2, a3, b0, b1) \
    asm volatile("mma.sync.aligned.m16n8k16.row.col.f32.bf16.bf16.f32 " \
        "{%0,%1,%2,%3}, {%4,%5,%6,%7}, {%8,%9}, {%0,%1,%2,%3};" \
        : "+f"((d)[0]), "+f"((d)[1]), "+f"((d)[2]), "+f"((d)[3]) \
        : "r"(a0), "r"(a1), "r"(a2), "r"(a3), "r"(b0), "r"(b1))

// split two floats into packed-bf16x2 hi and lo words (x -> lower half)
__device__ __forceinline__ void split2(float x, float y, uint32_t &hi, uint32_t &lo) {
    __nv_bfloat16 hx = __float2bfloat16(x);
    __nv_bfloat16 hy = __float2bfloat16(y);
    float rx = x - __bfloat162float(hx);
    float ry = y - __bfloat162float(hy);
    __nv_bfloat162 h; h.x = hx; h.y = hy;
    __nv_bfloat162 l; l.x = __float2bfloat16(rx); l.y = __float2bfloat16(ry);
    hi = *(uint32_t*)&h;
    lo = *(uint32_t*)&l;
}

// ---------------- RoPE tables --------------------------------------------------
__global__ void rope_table_kernel() {
    int idx = blockIdx.x * blockDim.x + threadIdx.x;
    int t = idx >> 5;
    int i = idx & 31;
    double inv = pow(10000.0, -((double)(2 * i)) / 64.0);
    double ang = (double)t * inv;
    g_cos[idx] = (float)cos(ang);
    g_sin[idx] = (float)sin(ang);
}

// ---------------- fp32 -> bf16 hi/lo split -------------------------------------
__global__ void cvt_kernel(const float2* __restrict__ src, int sel, int n2) {
    int i = blockIdx.x * blockDim.x + threadIdx.x;
    if (i >= n2) return;
    __nv_bfloat162* hi;
    __nv_bfloat162* lo;
    if (sel == 0)      { hi = (__nv_bfloat162*)gx_hi;   lo = (__nv_bfloat162*)gx_lo; }
    else               { hi = (__nv_bfloat162*)(gw_hi + ((size_t)(sel - 1) << 20));
                         lo = (__nv_bfloat162*)(gw_lo + ((size_t)(sel - 1) << 20)); }
    float2 v = src[i];
    uint32_t h, l;
    split2(v.x, v.y, h, l);
    *(uint32_t*)&hi[i] = h;
    *(uint32_t*)&lo[i] = l;
}

// ---------------- mma.sync bf16 split GEMM: C = A * W^T ------------------------
#define ROWB     144
#define TILE_B   (128 * ROWB)
#define STAGE_B  (4 * TILE_B)
#define GEMM_SMEM (2 * STAGE_B)

template <int QKV>
__global__ void __launch_bounds__(256, 1)
mma_gemm(float* __restrict__ Cout)
{
    extern __shared__ char smem_raw[];
    const uint32_t sb = smem_u32(smem_raw);

    const int tid = threadIdx.x;
    const int wid = tid >> 5;
    const int lid = tid & 31;
    const int n0 = blockIdx.x * 128;
    const int m0 = blockIdx.y * 128;
    const int z  = QKV ? (int)blockIdx.z : 3;

    const __nv_bfloat16* Ah = QKV ? gx_hi : gctx_hi;
    const __nv_bfloat16* Al = QKV ? gx_lo : gctx_lo;
    const __nv_bfloat16* Wh = gw_hi + ((size_t)z << 20);
    const __nv_bfloat16* Wl = gw_lo + ((size_t)z << 20);

    const __nv_bfloat16* Ah_m = Ah + (size_t)m0 * DMD;
    const __nv_bfloat16* Al_m = Al + (size_t)m0 * DMD;
    const __nv_bfloat16* Wh_n = Wh + (size_t)n0 * DMD;
    const __nv_bfloat16* Wl_n = Wl + (size_t)n0 * DMD;

    const int llr = tid >> 3;
    const int llc = tid & 7;

    auto load_chunk = [&](int kc, int s) {
        const uint32_t stage = sb + (uint32_t)s * STAGE_B;
        const size_t koff = (size_t)kc * 64 + (size_t)llc * 8;
#pragma unroll
        for (int it = 0; it < 16; ++it) {
            const __nv_bfloat16* base =
                (it < 4) ? Ah_m : (it < 8) ? Al_m : (it < 12) ? Wh_n : Wl_n;
            const int r = (it & 3) * 32 + llr;
            const uint32_t dst = stage + (uint32_t)(it >> 2) * TILE_B
                               + (uint32_t)r * ROWB + (uint32_t)llc * 16;
            cp_async16(dst, base + (size_t)r * DMD + koff);
        }
        CP_COMMIT();
    };

    const int wm = wid >> 2;
    const int wn = wid & 3;
    const int lt  = lid >> 3;
    const int lrw = lid & 7;

    const uint32_t a_off = (uint32_t)(wm * 64 + (lt & 1) * 8 + lrw) * ROWB
                         + (uint32_t)(lt >> 1) * 16;
    const uint32_t b_off = (uint32_t)(wn * 32 + (lt & 1) * 8 + lrw) * ROWB
                         + (uint32_t)(lt >> 1) * 16;

    float acc[4][4][4];
#pragma unroll
    for (int i = 0; i < 4; i++)
#pragma unroll
        for (int j = 0; j < 4; j++)
#pragma unroll
            for (int r = 0; r < 4; r++) acc[i][j][r] = 0.0f;

    load_chunk(0, 0);

    for (int c = 0; c < 16; ++c) {
        const int s = c & 1;
        if (c < 15) {
            load_chunk(c + 1, s ^ 1);
            CP_WAIT(1);
        } else {
            CP_WAIT(0);
        }
        __syncthreads();

        const uint32_t stage = sb + (uint32_t)s * STAGE_B;
        const uint32_t ah_base = stage + a_off;
        const uint32_t al_base = stage + TILE_B + a_off;
        const uint32_t bh_base = stage + 2 * TILE_B + b_off;
        const uint32_t bl_base = stage + 3 * TILE_B + b_off;

#pragma unroll
        for (int kk = 0; kk < 4; ++kk) {
            const uint32_t kb = (uint32_t)kk * 32;
            uint32_t ah[4][4], al[4][4], bh[2][4], bl[2][4];
#pragma unroll
            for (int mf = 0; mf < 4; ++mf) {
                LDMX4(ah[mf][0], ah[mf][1], ah[mf][2], ah[mf][3],
                      ah_base + (uint32_t)mf * (16 * ROWB) + kb);
                LDMX4(al[mf][0], al[mf][1], al[mf][2], al[mf][3],
                      al_base + (uint32_t)mf * (16 * ROWB) + kb);
            }
#pragma unroll
            for (int nn = 0; nn < 2; ++nn) {
                LDMX4(bh[nn][0], bh[nn][1], bh[nn][2], bh[nn][3],
                      bh_base + (uint32_t)nn * (16 * ROWB) + kb);
                LDMX4(bl[nn][0], bl[nn][1], bl[nn][2], bl[nn][3],
                      bl_base + (uint32_t)nn * (16 * ROWB) + kb);
            }
#pragma unroll
            for (int mf = 0; mf < 4; ++mf) {
#pragma unroll
                for (int nf = 0; nf < 4; ++nf) {
                    const int nn = nf >> 1;
                    const int sel = nf & 1;
                    MMA_BF16(acc[mf][nf], ah[mf][0], ah[mf][1], ah[mf][2], ah[mf][3],
                             bh[nn][sel], bh[nn][2 + sel]);
                    MMA_BF16(acc[mf][nf], ah[mf][0], ah[mf][1], ah[mf][2], ah[mf][3],
                             bl[nn][sel], bl[nn][2 + sel]);
                    MMA_BF16(acc[mf][nf], al[mf][0], al[mf][1], al[mf][2], al[mf][3],
                             bh[nn][sel], bh[nn][2 + sel]);
                }
            }
        }
        __syncthreads();
    }

    // ---------------- epilogue ----------------
    const int rbase = m0 + wm * 64 + (lid >> 2);
    const int cbase = n0 + wn * 32 + (lid & 3) * 2;

#pragma unroll
    for (int mf = 0; mf < 4; ++mf) {
#pragma unroll
        for (int nf = 0; nf < 4; ++nf) {
#pragma unroll
            for (int half = 0; half < 2; ++half) {
                const int m = rbase + mf * 16 + half * 8;
                const int n = cbase + nf * 8;
                const float x = acc[mf][nf][half * 2 + 0];
                const float y = acc[mf][nf][half * 2 + 1];
                if (QKV == 0) {
                    *(float2*)(Cout + (size_t)m * DMD + n) = make_float2(x, y);
                } else {
                    const int b = m >> 11;
                    const int t = m & (TT - 1);
                    const int h = n >> 6;
                    const int d = n & 63;
                    const size_t bh = (size_t)(b * HH + h);
                    if (z < 2) {
                        const float cs = g_cos[t * 32 + (d >> 1)];
                        const float sn = g_sin[t * 32 + (d >> 1)];
                        float rx = x * cs - y * sn;
                        float ry = x * sn + y * cs;
                        if (z == 0) { rx *= 0.125f; ry *= 0.125f; }   // attn scale folded into Q
                        uint32_t hv, lv;
                        split2(rx, ry, hv, lv);
                        const size_t idx = (bh * TT + t) * DKD + d;
                        if (z == 0) {
                            *(uint32_t*)(g_qh + idx) = hv;
                            *(uint32_t*)(g_ql + idx) = lv;
                        } else {
                            *(uint32_t*)(g_kh + idx) = hv;
                            *(uint32_t*)(g_kl + idx) = lv;
                        }
                    } else {
                        // V transposed: [b,h,d,t]
                        __nv_bfloat16 hx = __float2bfloat16(x);
                        __nv_bfloat16 hy = __float2bfloat16(y);
                        const size_t ix = (bh * DKD + d) * TT + t;
                        g_vth[ix]      = hx;
                        g_vtl[ix]      = __float2bfloat16(x - __bfloat162float(hx));
                        g_vth[ix + TT] = hy;
                        g_vtl[ix + TT] = __float2bfloat16(y - __bfloat162float(hy));
                    }
                }
            }
        }
    }
}

// ---------------- tensor-core causal flash attention ---------------------------
// 64-query tile per CTA, 4 warps x 16 rows. K/V(T) 64-key tiles double-buffered.
#define AROWB 144
#define ATILE (64 * AROWB)          // 9216
#define ATT_SMEM (10 * ATILE)       // Qh,Ql + 2 stages * (Kh,Kl,Vth,Vtl)

__global__ void __launch_bounds__(128, 1)
attn_kernel()
{
    extern __shared__ char smem_raw[];
    const uint32_t sb = smem_u32(smem_raw);
    const uint32_t stages = sb + 2 * ATILE;

    const int qt  = blockIdx.x;          // 0..31
    const int h   = blockIdx.y;
    const int b   = blockIdx.z;
    const int tid = threadIdx.x;
    const int wq  = tid >> 5;            // warp -> 16 query rows
    const int lid = tid & 31;

    const size_t bh = (size_t)(b * HH + h);
    const __nv_bfloat16* qh_g = g_qh + (bh * TT + (size_t)qt * 64) * DKD;
    const __nv_bfloat16* ql_g = g_ql + (bh * TT + (size_t)qt * 64) * DKD;
    const __nv_bfloat16* kh_g = g_kh + bh * TT * DKD;
    const __nv_bfloat16* kl_g = g_kl + bh * TT * DKD;
    const __nv_bfloat16* vh_g = g_vth + bh * DKD * TT;
    const __nv_bfloat16* vl_g = g_vtl + bh * DKD * TT;

    // ---- load Q tile (hi/lo), one commit group ----
#pragma unroll
    for (int i = 0; i < 4; ++i) {
        int cid = i * 128 + tid;         // 0..511
        int r = cid >> 3, c = cid & 7;
        cp_async16(sb + (uint32_t)r * AROWB + (uint32_t)c * 16,
                   qh_g + (size_t)r * DKD + c * 8);
        cp_async16(sb + ATILE + (uint32_t)r * AROWB + (uint32_t)c * 16,
                   ql_g + (size_t)r * DKD + c * 8);
    }
    CP_COMMIT();

    auto load_kv = [&](int kt, int s) {
        const uint32_t stage = stages + (uint32_t)s * (4 * ATILE);
#pragma unroll
        for (int i = 0; i < 4; ++i) {
            int cid = i * 128 + tid;     // 0..511
            int r = cid >> 3, c = cid & 7;
            const uint32_t so = (uint32_t)r * AROWB + (uint32_t)c * 16;
            const size_t kk = (size_t)(kt * 64 + r) * DKD + c * 8;
            const size_t vv = (size_t)r * TT + kt * 64 + c * 8;
            cp_async16(stage + so,             kh_g + kk);
            cp_async16(stage + ATILE + so,     kl_g + kk);
            cp_async16(stage + 2 * ATILE + so, vh_g + vv);
            cp_async16(stage + 3 * ATILE + so, vl_g + vv);
        }
        CP_COMMIT();
    };

    const int lt  = lid >> 3;
    const int lrw = lid & 7;
    const uint32_t a_off = (uint32_t)(wq * 16 + (lt & 1) * 8 + lrw) * AROWB
                         + (uint32_t)(lt >> 1) * 16;
    // B fragment row offsets for 16-row group nn
    uint32_t bn_off[4];
#pragma unroll
    for (int nn = 0; nn < 4; ++nn)
        bn_off[nn] = (uint32_t)(nn * 16 + (lt & 1) * 8 + lrw) * AROWB
                   + (uint32_t)(lt >> 1) * 16;

    load_kv(0, 0);

    // wait Q (group 0 of 2 pending after load_kv(0)); then pull Q frags
    CP_WAIT(1);
    __syncthreads();
    uint32_t qfh[4][4], qfl[4][4];
#pragma unroll
    for (int ks = 0; ks < 4; ++ks) {
        LDMX4(qfh[ks][0], qfh[ks][1], qfh[ks][2], qfh[ks][3], sb + a_off + ks * 32);
        LDMX4(qfl[ks][0], qfl[ks][1], qfl[ks][2], qfl[ks][3], sb + ATILE + a_off + ks * 32);
    }

    float O[8][4];
#pragma unroll
    for (int i = 0; i < 8; ++i)
#pragma unroll
        for (int j = 0; j < 4; ++j) O[i][j] = 0.0f;
    float m0v = -1e30f, m1v = -1e30f, l0 = 0.0f, l1 = 0.0f;

    for (int kt = 0; kt <= qt; ++kt) {
        const int s = kt & 1;
        if (kt < qt) {
            load_kv(kt + 1, s ^ 1);
            CP_WAIT(1);
        } else {
            CP_WAIT(0);
        }
        __syncthreads();

        const uint32_t stage = stages + (uint32_t)s * (4 * ATILE);

        // ---- S = Q K^T (3-pass split) ----
        float S[8][4];
#pragma unroll
        for (int i = 0; i < 8; ++i)
#pragma unroll
            for (int j = 0; j < 4; ++j) S[i][j] = 0.0f;

#pragma unroll
        for (int ks = 0; ks < 4; ++ks) {
            uint32_t kh[4][4], kl[4][4];
#pragma unroll
            for (int nn = 0; nn < 4; ++nn) {
                LDMX4(kh[nn][0], kh[nn][1], kh[nn][2], kh[nn][3],
                      stage + bn_off[nn] + ks * 32);
                LDMX4(kl[nn][0], kl[nn][1], kl[nn][2], kl[nn][3],
                      stage + ATILE + bn_off[nn] + ks * 32);
            }
#pragma unroll
            for (int nf = 0; nf < 8; ++nf) {
                const int nn = nf >> 1;
                const int sel = nf & 1;
                MMA_BF16(S[nf], qfh[ks][0], qfh[ks][1], qfh[ks][2], qfh[ks][3],
                         kh[nn][sel], kh[nn][2 + sel]);
                MMA_BF16(S[nf], qfh[ks][0], qfh[ks][1], qfh[ks][2], qfh[ks][3],
                         kl[nn][sel], kl[nn][2 + sel]);
                MMA_BF16(S[nf], qfl[ks][0], qfl[ks][1], qfl[ks][2], qfl[ks][3],
                         kh[nn][sel], kh[nn][2 + sel]);
            }
        }

        // ---- causal mask on diagonal tile ----
        if (kt == qt) {
            const int row0 = wq * 16 + (lid >> 2);
            const int colb = (lid & 3) * 2;
#pragma unroll
            for (int nf = 0; nf < 8; ++nf) {
                const int c0 = nf * 8 + colb;
                if (c0     > row0)     S[nf][0] = -1e30f;
                if (c0 + 1 > row0)     S[nf][1] = -1e30f;
                if (c0     > row0 + 8) S[nf][2] = -1e30f;
                if (c0 + 1 > row0 + 8) S[nf][3] = -1e30f;
            }
        }

        // ---- online softmax ----
        float r0 = -1e30f, r1 = -1e30f;
#pragma unroll
        for (int nf = 0; nf < 8; ++nf) {
            r0 = fmaxf(r0, fmaxf(S[nf][0], S[nf][1]));
            r1 = fmaxf(r1, fmaxf(S[nf][2], S[nf][3]));
        }
        r0 = fmaxf(r0, __shfl_xor_sync(0xffffffffu, r0, 1));
        r0 = fmaxf(r0, __shfl_xor_sync(0xffffffffu, r0, 2));
        r1 = fmaxf(r1, __shfl_xor_sync(0xffffffffu, r1, 1));
        r1 = fmaxf(r1, __shfl_xor_sync(0xffffffffu, r1, 2));

        const float nm0 = fmaxf(m0v, r0);
        const float nm1 = fmaxf(m1v, r1);
        const float a0 = __expf(m0v - nm0);
        const float a1 = __expf(m1v - nm1);
        m0v = nm0; m1v = nm1;

        float rs0 = 0.0f, rs1 = 0.0f;
#pragma unroll
        for (int nf = 0; nf < 8; ++nf) {
            S[nf][0] = __expf(S[nf][0] - m0v);
            S[nf][1] = __expf(S[nf][1] - m0v);
            S[nf][2] = __expf(S[nf][2] - m1v);
            S[nf][3] = __expf(S[nf][3] - m1v);
            rs0 += S[nf][0] + S[nf][1];
            rs1 += S[nf][2] + S[nf][3];
        }
        rs0 += __shfl_xor_sync(0xffffffffu, rs0, 1);
        rs0 += __shfl_xor_sync(0xffffffffu, rs0, 2);
        rs1 += __shfl_xor_sync(0xffffffffu, rs1, 1);
        rs1 += __shfl_xor_sync(0xffffffffu, rs1, 2);
        l0 = l0 * a0 + rs0;
        l1 = l1 * a1 + rs1;

#pragma unroll
        for (int nf = 0; nf < 8; ++nf) {
            O[nf][0] *= a0; O[nf][1] *= a0;
            O[nf][2] *= a1; O[nf][3] *= a1;
        }

        // ---- PV (3-pass split): A = P frags (from S), B = V^T tiles ----
#pragma unroll
        for (int kb2 = 0; kb2 < 4; ++kb2) {
            uint32_t ph[4], pl[4];
            split2(S[2 * kb2][0],     S[2 * kb2][1],     ph[0], pl[0]);
            split2(S[2 * kb2][2],     S[2 * kb2][3],     ph[1], pl[1]);
            split2(S[2 * kb2 + 1][0], S[2 * kb2 + 1][1], ph[2], pl[2]);
            split2(S[2 * kb2 + 1][2], S[2 * kb2 + 1][3], ph[3], pl[3]);

            uint32_t vh[4][4], vl[4][4];
#pragma unroll
            for (int nn = 0; nn < 4; ++nn) {
                LDMX4(vh[nn][0], vh[nn][1], vh[nn][2], vh[nn][3],
                      stage + 2 * ATILE + bn_off[nn] + kb2 * 32);
                LDMX4(vl[nn][0], vl[nn][1], vl[nn][2], vl[nn][3],
                      stage + 3 * ATILE + bn_off[nn] + kb2 * 32);
            }
#pragma unroll
            for (int nf = 0; nf < 8; ++nf) {
                const int nn = nf >> 1;
                const int sel = nf & 1;
                MMA_BF16(O[nf], ph[0], ph[1], ph[2], ph[3],
                         vh[nn][sel], vh[nn][2 + sel]);
                MMA_BF16(O[nf], ph[0], ph[1], ph[2], ph[3],
                         vl[nn][sel], vl[nn][2 + sel]);
                MMA_BF16(O[nf], pl[0], pl[1], pl[2], pl[3],
                         vh[nn][sel], vh[nn][2 + sel]);
            }
        }
        __syncthreads();
    }

    // ---- epilogue: ctx hi/lo bf16 ----
    const float i0 = 1.0f / l0;
    const float i1 = 1.0f / l1;
    const int q0 = qt * 64 + wq * 16 + (lid >> 2);
    const int colb = (lid & 3) * 2;
#pragma unroll
    for (int nf = 0; nf < 8; ++nf) {
        const int d = nf * 8 + colb;
        uint32_t hv, lv;
        size_t idx = ((size_t)b * TT + q0) * DMD + h * DKD + d;
        split2(O[nf][0] * i0, O[nf][1] * i0, hv, lv);
        *(uint32_t*)(gctx_hi + idx) = hv;
        *(uint32_t*)(gctx_lo + idx) = lv;
        idx += (size_t)8 * DMD;
        split2(O[nf][2] * i1, O[nf][3] * i1, hv, lv);
        *(uint32_t*)(gctx_hi + idx) = hv;
        *(uint32_t*)(gctx_lo + idx) = lv;
    }
}

// ---------------- launch ---------------------------------------------------------
extern "C" void kernel_launch(void* const* d_in, const int* in_sizes, int n_in,
                              void* d_out, int out_size)
{
    const float* x   = (const float*)d_in[0];
    const float* w_q = (const float*)d_in[1];
    const float* w_k = (const float*)d_in[2];
    const float* w_v = (const float*)d_in[3];
    const float* w_o = (const float*)d_in[4];
    float* out = (float*)d_out;

    static int configured = 0;
    if (!configured) {
        cudaFuncSetAttribute(mma_gemm<1>, cudaFuncAttributeMaxDynamicSharedMemorySize, GEMM_SMEM);
        cudaFuncSetAttribute(mma_gemm<0>, cudaFuncAttributeMaxDynamicSharedMemorySize, GEMM_SMEM);
        cudaFuncSetAttribute(attn_kernel, cudaFuncAttributeMaxDynamicSharedMemorySize, ATT_SMEM);
        configured = 1;
    }

    rope_table_kernel<<<(TT * 32) / 256, 256>>>();

    const int NX2 = MTOT * DMD / 2;
    const int NW2 = DMD * DMD / 2;
    cvt_kernel<<<(NX2 + 255) / 256, 256>>>((const float2*)x,   0, NX2);
    cvt_kernel<<<(NW2 + 255) / 256, 256>>>((const float2*)w_q, 1, NW2);
    cvt_kernel<<<(NW2 + 255) / 256, 256>>>((const float2*)w_k, 2, NW2);
    cvt_kernel<<<(NW2 + 255) / 256, 256>>>((const float2*)w_v, 3, NW2);
    cvt_kernel<<<(NW2 + 255) / 256, 256>>>((const float2*)w_o, 4, NW2);

    // QKV projections (+RoPE, +scale, bf16 split, V transposed)
    mma_gemm<1><<<dim3(DMD / 128, MTOT / 128, 3), 256, GEMM_SMEM>>>(nullptr);

    // tensor-core causal attention -> gctx hi/lo
    attn_kernel<<<dim3(TT / 64, HH, BB), 128, ATT_SMEM>>>();

    // output projection
    mma_gemm<0><<<dim3(DMD / 128, MTOT / 128, 1), 256, GEMM_SMEM>>>(out);
}